// round 4
// baseline (speedup 1.0000x reference)
#include <cuda_runtime.h>
#include <math.h>
#include <stdint.h>

// Problem constants
#define BATCH 32
#define CDIM  256
#define HW    1024            // 32*32
#define NPOS  32768           // BATCH*HW
#define KCODE 1024
#define TOTAL 8388608         // BATCH*CDIM*HW

// Scratch (device globals; no allocation allowed)
__device__ int           g_idx[NPOS];
__device__ float         g_wsq[KCODE];
__device__ float         g_zsq[NPOS];
__device__ unsigned int  g_counts[KCODE];
__device__ float         g_partial[1024];

// ---------------------------------------------------------------------------
// Kernel 0: zero the count accumulator
// ---------------------------------------------------------------------------
__global__ void k_zero() {
    g_counts[threadIdx.x] = 0u;
}

// ---------------------------------------------------------------------------
// Kernel W: per-code squared norms. One warp per code.
// wsq enters dist through round_u(wsq); 1e-10 order-noise vs u=1.5e-5 grid
// is negligible (expected flips ~0.003).
// ---------------------------------------------------------------------------
__global__ __launch_bounds__(256) void k_wsq(const float* __restrict__ w) {
    int warp = (blockIdx.x * 256 + threadIdx.x) >> 5;   // 0..1023
    int lane = threadIdx.x & 31;
    const float* row = w + (size_t)warp * CDIM;
    float s = 0.f;
    #pragma unroll
    for (int j = 0; j < CDIM / 32; ++j) {
        float v = row[lane + j * 32];
        s = fmaf(v, v, s);
    }
    #pragma unroll
    for (int off = 16; off > 0; off >>= 1)
        s += __shfl_down_sync(0xFFFFFFFFu, s, off);
    if (lane == 0) g_wsq[warp] = s;
}

// ---------------------------------------------------------------------------
// Kernel Z: per-position ||z||^2. Only the binade of zsq matters (zsq cancels
// from the quantized comparison); any fp32-accurate order is fine.
// ---------------------------------------------------------------------------
__global__ __launch_bounds__(256) void k_zsq(const float* __restrict__ z) {
    __shared__ float sm[256][33];   // [channel][position], padded
    const int t   = threadIdx.x;
    const int n0  = blockIdx.x * 32;
    const int b   = n0 >> 10;
    const int hw0 = n0 & 1023;
    const float* zb = z + (size_t)b * (CDIM * HW) + hw0;

    #pragma unroll 8
    for (int it = 0; it < 32; ++it) {
        int idx = it * 256 + t;
        int c = idx >> 5, hwi = idx & 31;
        sm[c][hwi] = zb[(size_t)c * HW + hwi];
    }
    __syncthreads();

    const int wrp = t >> 5, lane = t & 31;
    for (int r = 0; r < 4; ++r) {
        const int hwi = wrp * 4 + r;
        float acc = 0.f;
        #pragma unroll
        for (int i = 0; i < 8; ++i) {
            float a = sm[32 * i + lane][hwi];
            acc = __fadd_rn(acc, __fmul_rn(a, a));
        }
        #pragma unroll
        for (int off = 16; off > 0; off >>= 1)
            acc = __fadd_rn(acc, __shfl_down_sync(0xFFFFFFFFu, acc, off));
        if (lane == 0) g_zsq[n0 + hwi] = acc;
    }
}

// ---------------------------------------------------------------------------
// Kernel A: fused fp32 GEMM + argmin with reference rounding.
// m = ascending-c single FMA chain (sgemm order). Block = 64 positions;
// K tiles of 64 codes; C chunks of 16; 4x4 register micro-tiles.
// dist = RN( RN(zsq_n - 2*m) + wsq_k ); argmin with lowest-index ties.
// ---------------------------------------------------------------------------
__global__ __launch_bounds__(256) void k_argmin(const float* __restrict__ z,
                                                const float* __restrict__ w) {
    __shared__ float zs[16][64];
    __shared__ float ws[16][64];
    __shared__ unsigned long long bests[64];

    const int t  = threadIdx.x;
    const int tx = t & 15;       // position group
    const int ty = t >> 4;       // code group

    const int n0  = blockIdx.x * 64;
    const int b   = n0 >> 10;
    const int hw0 = n0 & 1023;
    const float* zbase = z + (size_t)b * (CDIM * HW) + hw0;

    const int zl_c = t >> 4;          // channel within chunk
    const int zl_p = (t & 15) * 4;    // position quad
    const int wl_k = t >> 2;          // code
    const int wl_q = (t & 3) * 4;     // channel quad within chunk

    float zsqv[4];
    #pragma unroll
    for (int i = 0; i < 4; ++i) zsqv[i] = g_zsq[n0 + tx * 4 + i];

    float bestv[4] = {3.4e38f, 3.4e38f, 3.4e38f, 3.4e38f};
    int   bestk[4] = {0, 0, 0, 0};

    for (int kt = 0; kt < KCODE / 64; ++kt) {
        const int k0 = kt * 64;
        float acc[4][4];
        #pragma unroll
        for (int i = 0; i < 4; ++i)
            #pragma unroll
            for (int j = 0; j < 4; ++j) acc[i][j] = 0.f;

        for (int ct = 0; ct < CDIM / 16; ++ct) {
            const int c0 = ct * 16;
            __syncthreads();
            float4 zv = *(const float4*)(zbase + (size_t)(c0 + zl_c) * HW + zl_p);
            *(float4*)&zs[zl_c][zl_p] = zv;
            float4 wv = *(const float4*)(w + (size_t)(k0 + wl_k) * CDIM + c0 + wl_q);
            ws[wl_q + 0][wl_k] = wv.x;
            ws[wl_q + 1][wl_k] = wv.y;
            ws[wl_q + 2][wl_k] = wv.z;
            ws[wl_q + 3][wl_k] = wv.w;
            __syncthreads();

            // ascending-c sequential fp32 FMA chain (sgemm accumulation order)
            #pragma unroll
            for (int cc = 0; cc < 16; ++cc) {
                float4 zr = *(const float4*)&zs[cc][tx * 4];
                float4 wr = *(const float4*)&ws[cc][ty * 4];
                acc[0][0] = fmaf(zr.x, wr.x, acc[0][0]);
                acc[0][1] = fmaf(zr.x, wr.y, acc[0][1]);
                acc[0][2] = fmaf(zr.x, wr.z, acc[0][2]);
                acc[0][3] = fmaf(zr.x, wr.w, acc[0][3]);
                acc[1][0] = fmaf(zr.y, wr.x, acc[1][0]);
                acc[1][1] = fmaf(zr.y, wr.y, acc[1][1]);
                acc[1][2] = fmaf(zr.y, wr.z, acc[1][2]);
                acc[1][3] = fmaf(zr.y, wr.w, acc[1][3]);
                acc[2][0] = fmaf(zr.z, wr.x, acc[2][0]);
                acc[2][1] = fmaf(zr.z, wr.y, acc[2][1]);
                acc[2][2] = fmaf(zr.z, wr.z, acc[2][2]);
                acc[2][3] = fmaf(zr.z, wr.w, acc[2][3]);
                acc[3][0] = fmaf(zr.w, wr.x, acc[3][0]);
                acc[3][1] = fmaf(zr.w, wr.y, acc[3][1]);
                acc[3][2] = fmaf(zr.w, wr.z, acc[3][2]);
                acc[3][3] = fmaf(zr.w, wr.w, acc[3][3]);
            }
        }

        // dist = RN( RN(zsq - 2*acc) + wsq )  — reference rounding order
        // (2*acc exact; fmaf gives the single rounding of zsq - 2*acc)
        #pragma unroll
        for (int j = 0; j < 4; ++j) {
            const int k = k0 + ty * 4 + j;
            const float wsq = g_wsq[k];
            #pragma unroll
            for (int i = 0; i < 4; ++i) {
                float t1 = fmaf(-2.0f, acc[i][j], zsqv[i]);
                float sc = __fadd_rn(t1, wsq);
                if (sc < bestv[i]) { bestv[i] = sc; bestk[i] = k; }
            }
        }
    }

    if (t < 64) bests[t] = ~0ull;
    __syncthreads();
    #pragma unroll
    for (int i = 0; i < 4; ++i) {
        unsigned u = __float_as_uint(bestv[i]);
        u = (u & 0x80000000u) ? ~u : (u | 0x80000000u);   // order-preserving map
        unsigned long long e = ((unsigned long long)u << 32) | (unsigned)bestk[i];
        atomicMin(&bests[tx * 4 + i], e);
    }
    __syncthreads();
    if (t < 64) {
        int idx = (int)(bests[t] & 0xFFFFFFFFull);
        g_idx[n0 + t] = idx;
        atomicAdd(&g_counts[idx], 1u);
    }
}

// ---------------------------------------------------------------------------
// Kernel B: gather codebook, straight-through output, squared-diff partials.
// out = RN(z + RN(q - z)) — exact reference elementwise formula.
// ---------------------------------------------------------------------------
__global__ __launch_bounds__(256) void k_quant(const float* __restrict__ z,
                                               const float* __restrict__ w,
                                               float* __restrict__ out) {
    __shared__ float sm[256];
    float local = 0.f;
    for (int i = blockIdx.x * 256 + threadIdx.x; i < TOTAL; i += 1024 * 256) {
        const int hw = i & 1023;
        const int c  = (i >> 10) & 255;
        const int b  = i >> 18;
        const int idx = g_idx[b * HW + hw];
        const float q = w[(size_t)idx * CDIM + c];
        const float zz = z[i];
        const float d = __fadd_rn(q, -zz);
        out[i] = __fadd_rn(zz, d);       // straight-through: z + sg(q - z)
        local = fmaf(d, d, local);
    }
    sm[threadIdx.x] = local;
    __syncthreads();
    for (int s = 128; s > 0; s >>= 1) {
        if (threadIdx.x < s) sm[threadIdx.x] += sm[threadIdx.x + s];
        __syncthreads();
    }
    if (threadIdx.x == 0) g_partial[blockIdx.x] = sm[0];
}

// ---------------------------------------------------------------------------
// Kernel C: finalize loss + perplexity
// ---------------------------------------------------------------------------
__global__ __launch_bounds__(1024) void k_final(float* __restrict__ out) {
    __shared__ float sm[1024];
    const int t = threadIdx.x;

    sm[t] = g_partial[t];
    __syncthreads();
    for (int s = 512; s > 0; s >>= 1) {
        if (t < s) sm[t] += sm[t + s];
        __syncthreads();
    }
    if (t == 0) {
        float m = sm[0] / (float)TOTAL;
        out[TOTAL] = m + 0.25f * m;      // q_latent + COMMITMENT_COST * e_latent
    }
    __syncthreads();

    float p = (float)g_counts[t] * (1.0f / (float)NPOS);
    sm[t] = p * logf(p + 1e-10f);
    __syncthreads();
    for (int s = 512; s > 0; s >>= 1) {
        if (t < s) sm[t] += sm[t + s];
        __syncthreads();
    }
    if (t == 0) out[TOTAL + 1] = expf(-sm[0]);
}

// ---------------------------------------------------------------------------
extern "C" void kernel_launch(void* const* d_in, const int* in_sizes, int n_in,
                              void* d_out, int out_size) {
    const float* z = (const float*)d_in[0];
    const float* w = (const float*)d_in[1];
    float* out = (float*)d_out;

    k_zero<<<1, 1024>>>();
    k_wsq<<<128, 256>>>(w);
    k_zsq<<<NPOS / 32, 256>>>(z);
    k_argmin<<<NPOS / 64, 256>>>(z, w);
    k_quant<<<1024, 256>>>(z, w, out);
    k_final<<<1, 1024>>>(out);
}

// round 5
// speedup vs baseline: 1.4487x; 1.4487x over previous
#include <cuda_runtime.h>
#include <math.h>
#include <stdint.h>

// Problem constants
#define BATCH 32
#define CDIM  256
#define HW    1024            // 32*32
#define NPOS  32768           // BATCH*HW
#define KCODE 1024
#define TOTAL 8388608         // BATCH*CDIM*HW

// Scratch (device globals; no allocation allowed)
__device__ int           g_idx[NPOS];
__device__ float         g_wsq[KCODE];
__device__ float         g_zsq[NPOS];
__device__ unsigned int  g_counts[KCODE];
__device__ float         g_partial[1024];

// Packed fp32x2 FMA (Blackwell): two independent RN FMAs per instruction.
// Bit-identical to two scalar fmaf chains.
#define FMA2(d, a, b, c) \
    asm("fma.rn.f32x2 %0, %1, %2, %3;" : "=l"(d) : "l"(a), "l"(b), "l"(c))
#define PACK_DUP(d, s) \
    asm("mov.b64 %0, {%1, %1};" : "=l"(d) : "r"(__float_as_uint(s)))
#define UNPACK2(lo, hi, s) \
    asm("mov.b64 {%0, %1}, %2;" : "=f"(lo), "=f"(hi) : "l"(s))

// ---------------------------------------------------------------------------
// Kernel 0: zero the count accumulator
// ---------------------------------------------------------------------------
__global__ void k_zero() {
    g_counts[threadIdx.x] = 0u;
}

// ---------------------------------------------------------------------------
// Kernel W: per-code squared norms. One warp per code.
// ---------------------------------------------------------------------------
__global__ __launch_bounds__(256) void k_wsq(const float* __restrict__ w) {
    int warp = (blockIdx.x * 256 + threadIdx.x) >> 5;   // 0..1023
    int lane = threadIdx.x & 31;
    const float* row = w + (size_t)warp * CDIM;
    float s = 0.f;
    #pragma unroll
    for (int j = 0; j < CDIM / 32; ++j) {
        float v = row[lane + j * 32];
        s = fmaf(v, v, s);
    }
    #pragma unroll
    for (int off = 16; off > 0; off >>= 1)
        s += __shfl_down_sync(0xFFFFFFFFu, s, off);
    if (lane == 0) g_wsq[warp] = s;
}

// ---------------------------------------------------------------------------
// Kernel Z: per-position ||z||^2 (fp32-accurate; binade is what matters).
// ---------------------------------------------------------------------------
__global__ __launch_bounds__(256) void k_zsq(const float* __restrict__ z) {
    __shared__ float sm[256][33];   // [channel][position], padded
    const int t   = threadIdx.x;
    const int n0  = blockIdx.x * 32;
    const int b   = n0 >> 10;
    const int hw0 = n0 & 1023;
    const float* zb = z + (size_t)b * (CDIM * HW) + hw0;

    #pragma unroll 8
    for (int it = 0; it < 32; ++it) {
        int idx = it * 256 + t;
        int c = idx >> 5, hwi = idx & 31;
        sm[c][hwi] = zb[(size_t)c * HW + hwi];
    }
    __syncthreads();

    const int wrp = t >> 5, lane = t & 31;
    for (int r = 0; r < 4; ++r) {
        const int hwi = wrp * 4 + r;
        float acc = 0.f;
        #pragma unroll
        for (int i = 0; i < 8; ++i) {
            float a = sm[32 * i + lane][hwi];
            acc = __fadd_rn(acc, __fmul_rn(a, a));
        }
        #pragma unroll
        for (int off = 16; off > 0; off >>= 1)
            acc = __fadd_rn(acc, __shfl_down_sync(0xFFFFFFFFu, acc, off));
        if (lane == 0) g_zsq[n0 + hwi] = acc;
    }
}

// ---------------------------------------------------------------------------
// Kernel A: fused fp32 GEMM + argmin using packed fp32x2 FMA.
// Block tile: 128 positions x 128 codes. 256 threads, each 8 pos x 8 codes
// (positions split as tx*4..+3 and 64+tx*4..+3; codes likewise on ty).
// acc chains remain exact ascending-c scalar-RN FMA chains (f32x2 halves
// are independent), so dist bits match the reference:
//   dist = RN( RN(zsq - 2*m) + wsq ), argmin ties -> lowest index.
// ---------------------------------------------------------------------------
__global__ __launch_bounds__(256, 2) void k_argmin(const float* __restrict__ z,
                                                   const float* __restrict__ w) {
    __shared__ float zs[16][128];
    __shared__ float ws[16][128];
    __shared__ unsigned long long bests[128];

    const int t  = threadIdx.x;
    const int tx = t & 15;       // position group
    const int ty = t >> 4;       // code group

    const int n0  = blockIdx.x * 128;
    const int b   = n0 >> 10;
    const int hw0 = n0 & 1023;
    const float* zbase = z + (size_t)b * (CDIM * HW) + hw0;

    // staging indices (float4 granularity)
    const int zc0 = t >> 5;            // 0..7   (z chunk row, first load)
    const int zp0 = (t & 31) * 4;      // 0..124 (z position col)
    const int wk  = t >> 1;            // 0..127 (w code row)
    const int wq  = (t & 1) * 8;       // 0 or 8 (channel offset within chunk)

    float bestv[8];
    int   bestk[8];
    #pragma unroll
    for (int i = 0; i < 8; ++i) { bestv[i] = 3.4e38f; bestk[i] = 0; }

    for (int kt = 0; kt < KCODE / 128; ++kt) {
        const int k0 = kt * 128;
        unsigned long long acc2[4][8];
        #pragma unroll
        for (int i = 0; i < 4; ++i)
            #pragma unroll
            for (int j = 0; j < 8; ++j) acc2[i][j] = 0ull;

        for (int ct = 0; ct < CDIM / 16; ++ct) {
            const int c0 = ct * 16;
            __syncthreads();
            // stage z chunk [16 c][128 pos] (layout matches gmem: direct float4)
            {
                float4 v0 = *(const float4*)(zbase + (size_t)(c0 + zc0) * HW + zp0);
                *(float4*)&zs[zc0][zp0] = v0;
                float4 v1 = *(const float4*)(zbase + (size_t)(c0 + 8 + zc0) * HW + zp0);
                *(float4*)&zs[8 + zc0][zp0] = v1;
            }
            // stage w chunk transposed [16 c][128 k]
            {
                float4 wv0 = *(const float4*)(w + (size_t)(k0 + wk) * CDIM + c0 + wq);
                ws[wq + 0][wk] = wv0.x;
                ws[wq + 1][wk] = wv0.y;
                ws[wq + 2][wk] = wv0.z;
                ws[wq + 3][wk] = wv0.w;
                float4 wv1 = *(const float4*)(w + (size_t)(k0 + wk) * CDIM + c0 + wq + 4);
                ws[wq + 4][wk] = wv1.x;
                ws[wq + 5][wk] = wv1.y;
                ws[wq + 6][wk] = wv1.z;
                ws[wq + 7][wk] = wv1.w;
            }
            __syncthreads();

            #pragma unroll
            for (int cc = 0; cc < 16; ++cc) {
                // position pairs, pre-packed by layout (LDS.128 -> 2 x f32x2)
                ulonglong2 za = *(const ulonglong2*)&zs[cc][tx * 4];
                ulonglong2 zb2 = *(const ulonglong2*)&zs[cc][64 + tx * 4];
                float4 wa = *(const float4*)&ws[cc][ty * 4];
                float4 wb = *(const float4*)&ws[cc][64 + ty * 4];
                unsigned long long wd[8];
                PACK_DUP(wd[0], wa.x); PACK_DUP(wd[1], wa.y);
                PACK_DUP(wd[2], wa.z); PACK_DUP(wd[3], wa.w);
                PACK_DUP(wd[4], wb.x); PACK_DUP(wd[5], wb.y);
                PACK_DUP(wd[6], wb.z); PACK_DUP(wd[7], wb.w);
                #pragma unroll
                for (int j = 0; j < 8; ++j) {
                    FMA2(acc2[0][j], za.x,  wd[j], acc2[0][j]);
                    FMA2(acc2[1][j], za.y,  wd[j], acc2[1][j]);
                    FMA2(acc2[2][j], zb2.x, wd[j], acc2[2][j]);
                    FMA2(acc2[3][j], zb2.y, wd[j], acc2[3][j]);
                }
            }
        }

        // epilogue: dist = RN( RN(zsq - 2*m) + wsq ), ascending k per thread
        #pragma unroll
        for (int j = 0; j < 8; ++j) {
            const int k = k0 + ((j < 4) ? (ty * 4 + j) : (64 + ty * 4 + (j - 4)));
            const float wsq = g_wsq[k];
            #pragma unroll
            for (int i2 = 0; i2 < 4; ++i2) {
                float m0, m1;
                UNPACK2(m0, m1, acc2[i2][j]);
                const int lpA = (i2 < 2) ? (tx * 4 + i2 * 2) : (64 + tx * 4 + (i2 - 2) * 2);
                const float zsqA = g_zsq[n0 + lpA];
                const float zsqB = g_zsq[n0 + lpA + 1];
                float t1a = fmaf(-2.0f, m0, zsqA);
                float sca = __fadd_rn(t1a, wsq);
                const int ia = i2 * 2;
                if (sca < bestv[ia]) { bestv[ia] = sca; bestk[ia] = k; }
                float t1b = fmaf(-2.0f, m1, zsqB);
                float scb = __fadd_rn(t1b, wsq);
                if (scb < bestv[ia + 1]) { bestv[ia + 1] = scb; bestk[ia + 1] = k; }
            }
        }
    }

    if (t < 128) bests[t] = ~0ull;
    __syncthreads();
    #pragma unroll
    for (int i = 0; i < 8; ++i) {
        const int lp = (i < 4) ? (tx * 4 + i) : (64 + tx * 4 + (i - 4));
        unsigned u = __float_as_uint(bestv[i]);
        u = (u & 0x80000000u) ? ~u : (u | 0x80000000u);   // order-preserving map
        unsigned long long e = ((unsigned long long)u << 32) | (unsigned)bestk[i];
        atomicMin(&bests[lp], e);
    }
    __syncthreads();
    if (t < 128) {
        int idx = (int)(bests[t] & 0xFFFFFFFFull);
        g_idx[n0 + t] = idx;
        atomicAdd(&g_counts[idx], 1u);
    }
}

// ---------------------------------------------------------------------------
// Kernel B: gather codebook, straight-through output, squared-diff partials.
// float4 over hw (4 consecutive positions share b, c).
// out = RN(z + RN(q - z)) — exact reference elementwise formula.
// ---------------------------------------------------------------------------
__global__ __launch_bounds__(256) void k_quant(const float* __restrict__ z,
                                               const float* __restrict__ w,
                                               float* __restrict__ out) {
    __shared__ float sm[256];
    float local = 0.f;
    for (int i4 = blockIdx.x * 256 + threadIdx.x; i4 < TOTAL / 4; i4 += 1024 * 256) {
        const int i  = i4 * 4;
        const int hw = i & 1023;
        const int c  = (i >> 10) & 255;
        const int b  = i >> 18;
        const int* ib = &g_idx[b * HW + hw];
        float4 zz = *(const float4*)(z + i);
        float q0 = w[(size_t)ib[0] * CDIM + c];
        float q1 = w[(size_t)ib[1] * CDIM + c];
        float q2 = w[(size_t)ib[2] * CDIM + c];
        float q3 = w[(size_t)ib[3] * CDIM + c];
        float4 o;
        float d;
        d = __fadd_rn(q0, -zz.x); o.x = __fadd_rn(zz.x, d); local = fmaf(d, d, local);
        d = __fadd_rn(q1, -zz.y); o.y = __fadd_rn(zz.y, d); local = fmaf(d, d, local);
        d = __fadd_rn(q2, -zz.z); o.z = __fadd_rn(zz.z, d); local = fmaf(d, d, local);
        d = __fadd_rn(q3, -zz.w); o.w = __fadd_rn(zz.w, d); local = fmaf(d, d, local);
        *(float4*)(out + i) = o;
    }
    sm[threadIdx.x] = local;
    __syncthreads();
    for (int s = 128; s > 0; s >>= 1) {
        if (threadIdx.x < s) sm[threadIdx.x] += sm[threadIdx.x + s];
        __syncthreads();
    }
    if (threadIdx.x == 0) g_partial[blockIdx.x] = sm[0];
}

// ---------------------------------------------------------------------------
// Kernel C: finalize loss + perplexity
// ---------------------------------------------------------------------------
__global__ __launch_bounds__(1024) void k_final(float* __restrict__ out) {
    __shared__ float sm[1024];
    const int t = threadIdx.x;

    sm[t] = g_partial[t];
    __syncthreads();
    for (int s = 512; s > 0; s >>= 1) {
        if (t < s) sm[t] += sm[t + s];
        __syncthreads();
    }
    if (t == 0) {
        float m = sm[0] / (float)TOTAL;
        out[TOTAL] = m + 0.25f * m;      // q_latent + COMMITMENT_COST * e_latent
    }
    __syncthreads();

    float p = (float)g_counts[t] * (1.0f / (float)NPOS);
    sm[t] = p * logf(p + 1e-10f);
    __syncthreads();
    for (int s = 512; s > 0; s >>= 1) {
        if (t < s) sm[t] += sm[t + s];
        __syncthreads();
    }
    if (t == 0) out[TOTAL + 1] = expf(-sm[0]);
}

// ---------------------------------------------------------------------------
extern "C" void kernel_launch(void* const* d_in, const int* in_sizes, int n_in,
                              void* d_out, int out_size) {
    const float* z = (const float*)d_in[0];
    const float* w = (const float*)d_in[1];
    float* out = (float*)d_out;

    k_zero<<<1, 1024>>>();
    k_wsq<<<128, 256>>>(w);
    k_zsq<<<NPOS / 32, 256>>>(z);
    k_argmin<<<NPOS / 128, 256>>>(z, w);
    k_quant<<<1024, 256>>>(z, w, out);
    k_final<<<1, 1024>>>(out);
}